// round 15
// baseline (speedup 1.0000x reference)
#include <cuda_runtime.h>
#include <cuda_fp16.h>
#include <mma.h>
#include <cstdint>

using namespace nvcuda;

#define MAXN 50000
#define IN_DIM 128
#define HID 96
#define EMAX 1048576
#define SCAN_CH 512
#define SCAN_MAXB 128

// Static scratch (no runtime allocation allowed)
__device__ __align__(16) __half g_zh[MAXN * HID];  // GEMM outputs (fp16)
__device__ __align__(16) __half g_hh[MAXN * HID];  // gather outputs (dinv*relu, fp16)
__device__ __align__(16) __half g_w1h[IN_DIM * HID];
__device__ __align__(16) __half g_w1l[IN_DIM * HID];
__device__ __align__(16) __half g_w2h[HID * HID];
__device__ __align__(16) __half g_w2l[HID * HID];
__device__ float g_s[MAXN];
__device__ float g_dinv[MAXN];
__device__ float g_invstd[IN_DIM];
__device__ float g_w3v[HID + 1];
__device__ int   g_cnt[MAXN];
__device__ int   g_rowptr[MAXN + 1];
__device__ int   g_cursor[MAXN];
__device__ int   g_bval[SCAN_MAXB];
__device__ int   g_bflag[SCAN_MAXB];
__device__ int   g_col[EMAX];

// ---------------------------------------------------------------------------
// Pre: zero cnt/flags, invstd, w3v, W1/W2 hi-lo conversion (one launch)
// ---------------------------------------------------------------------------
__global__ void __launch_bounds__(256)
k_pre(int* cnt, int n, int* bflag,
      const float* __restrict__ stdv, float* __restrict__ invstd,
      const float* __restrict__ W1, const float* __restrict__ W2,
      const float* __restrict__ W3, const float* __restrict__ b3,
      const float* __restrict__ Wout, const float* __restrict__ bout,
      float* __restrict__ w3v,
      __half* __restrict__ w1h, __half* __restrict__ w1l,
      __half* __restrict__ w2h, __half* __restrict__ w2l)
{
    int b = blockIdx.x, tid = threadIdx.x;
    int i = b * 256 + tid;
    if (i < n) cnt[i] = 0;
    if (b == 0 && tid < SCAN_MAXB) bflag[tid] = 0;
    if (b == 1 && tid < IN_DIM) invstd[tid] = 1.0f / stdv[tid];
    if (b == 2 || b == 3) {
        __shared__ float swout[HID];
        if (tid < HID) swout[tid] = Wout[2 * tid + 1];
        __syncthreads();
        int rl = tid >> 2, q = tid & 3;
        int r = (b - 2) * 48 + (rl < 48 ? rl : 47);
        float a = 0.f;
#pragma unroll 8
        for (int j = q * 24; j < q * 24 + 24; j++)
            a = fmaf(W3[r * HID + j], swout[j], a);
        a += __shfl_xor_sync(~0u, a, 1);
        a += __shfl_xor_sync(~0u, a, 2);
        if (q == 0 && rl < 48) w3v[r] = a;
        if (b == 2 && tid == 255) {
            float c = bout[1];
#pragma unroll 8
            for (int j = 0; j < HID; j++) c = fmaf(b3[j], swout[j], c);
            w3v[HID] = c;
        }
    }
    if (b >= 4 && b < 52) {
        int j = (b - 4) * 256 + tid;
        float wv = W1[j];
        __half h = __float2half_rn(wv);
        w1h[j] = h;
        w1l[j] = __float2half_rn(wv - __half2float(h));
    }
    if (b >= 52 && b < 88) {
        int j = (b - 52) * 256 + tid;
        float wv = W2[j];
        __half h = __float2half_rn(wv);
        w2h[j] = h;
        w2l[j] = __float2half_rn(wv - __half2float(h));
    }
}

__global__ void k_count(const int* __restrict__ ei, int E, int* cnt) {
    int t = blockIdx.x * blockDim.x + threadIdx.x;
    int e0 = t * 2, e1 = e0 + 1;
    int d0 = (e0 < E) ? ei[E + e0] : -1;
    int d1 = (e1 < E) ? ei[E + e1] : -1;
    if (d0 >= 0) atomicAdd(&cnt[d0], 1);
    if (d1 >= 0) atomicAdd(&cnt[d1], 1);
}

// ---------------------------------------------------------------------------
// Single-kernel scan (decoupled lookback)
// ---------------------------------------------------------------------------
__global__ void __launch_bounds__(256)
k_scan(const int* __restrict__ cnt, int n, int* __restrict__ rowptr,
       int* __restrict__ cursor, float* __restrict__ dinv,
       int* bval, int* bflag)
{
    __shared__ int wsum[8];
    __shared__ int s_base;
    int b = blockIdx.x, tid = threadIdx.x, lane = tid & 31, wid = tid >> 5;
    int i0 = b * SCAN_CH + 2 * tid;
    int c0 = (i0     < n) ? cnt[i0]     : 0;
    int c1 = (i0 + 1 < n) ? cnt[i0 + 1] : 0;
    int s = c0 + c1;
    int x = s;
#pragma unroll
    for (int d = 1; d < 32; d <<= 1) {
        int t = __shfl_up_sync(~0u, x, d);
        if (lane >= d) x += t;
    }
    if (lane == 31) wsum[wid] = x;
    __syncthreads();
    if (wid == 0 && lane < 8) {
        int ws = wsum[lane];
#pragma unroll
        for (int d = 1; d < 8; d <<= 1) {
            int t = __shfl_up_sync(0xFF, ws, d);
            if (lane >= d) ws += t;
        }
        wsum[lane] = ws;
    }
    __syncthreads();
    int ex_local = x - s + (wid ? wsum[wid - 1] : 0);
    int block_total = wsum[7];

    if (tid == 0) {
        atomicExch(&bval[b], block_total);
        __threadfence();
        atomicExch(&bflag[b], 1);
        if (b == 0) rowptr[0] = 0;
    }
    if (wid == 0) {
        int part = 0;
        for (int j = lane; j < b; j += 32) {
            while (atomicAdd(&bflag[j], 0) == 0) {}
            part += atomicAdd(&bval[j], 0);
        }
#pragma unroll
        for (int d = 16; d; d >>= 1) part += __shfl_xor_sync(~0u, part, d);
        if (lane == 0) s_base = part;
    }
    __syncthreads();
    int ex = ex_local + s_base;
    if (i0 < n) {
        cursor[i0]     = ex;
        rowptr[i0 + 1] = ex + c0;
        dinv[i0]       = rsqrtf((float)(c0 + 1));
    }
    if (i0 + 1 < n) {
        cursor[i0 + 1] = ex + c0;
        rowptr[i0 + 2] = ex + c0 + c1;
        dinv[i0 + 1]   = rsqrtf((float)(c1 + 1));
    }
}

__global__ void k_fill(const int* __restrict__ ei, int E,
                       int* __restrict__ cursor, int* __restrict__ col)
{
    int t = blockIdx.x * blockDim.x + threadIdx.x;
    int e0 = t * 2, e1 = e0 + 1;
    int s0 = 0, s1 = 0, d0 = -1, d1 = -1;
    if (e0 < E) { s0 = ei[e0]; d0 = ei[E + e0]; }
    if (e1 < E) { s1 = ei[e1]; d1 = ei[E + e1]; }
    int slot0 = (d0 >= 0) ? atomicAdd(&cursor[d0], 1) : 0;
    int slot1 = (d1 >= 0) ? atomicAdd(&cursor[d1], 1) : 0;
    if (d0 >= 0) col[slot0] = s0;
    if (d1 >= 0) col[slot1] = s1;
}

// ---------------------------------------------------------------------------
// GEMM1 (tensor, 3-pass hi/lo, register-prefetch pipelined):
// z = scaler(x) @ W1  (no dinv)
// ---------------------------------------------------------------------------
__global__ void __launch_bounds__(256)
k_gemm1(const float* __restrict__ A,
        const __half* __restrict__ Wh, const __half* __restrict__ Wl,
        const float* __restrict__ mean, const float* __restrict__ invstd,
        __half* __restrict__ out, int n)
{
    constexpr int AL = 72;
    constexpr int WL = 104;
    __shared__ __align__(16) __half As_hi[128 * AL];
    __shared__ __align__(16) __half As_lo[128 * AL];
    __shared__ __align__(16) __half Ws_hi[64 * WL];
    __shared__ __align__(16) __half Ws_lo[64 * WL];

    const int tid = threadIdx.x, w = tid >> 5;
    const int row0 = blockIdx.x * 128;
    const int arow = tid >> 1, ahalf = tid & 1;
    const int grow = row0 + arow;
    const bool aok = grow < n;
    const bool active = (row0 + w * 16) < n;

    wmma::fragment<wmma::accumulator, 16, 16, 16, float> acc[6];
#pragma unroll
    for (int c = 0; c < 6; c++) wmma::fill_fragment(acc[c], 0.0f);

    float4 cur[8];
    {
        const float* Ap = A + (size_t)grow * IN_DIM + ahalf * 32;
#pragma unroll
        for (int j = 0; j < 8; j++)
            cur[j] = aok ? *(const float4*)(Ap + j * 4)
                         : make_float4(0.f, 0.f, 0.f, 0.f);
    }

#pragma unroll
    for (int chunk = 0; chunk < 2; chunk++) {
        const int kc = chunk * 64;
#pragma unroll
        for (int jj = 0; jj < 4; jj++) {
            __half hi8[8], lo8[8];
#pragma unroll
            for (int j = 0; j < 2; j++) {
                float4 v = cur[jj * 2 + j];
                int kg = kc + ahalf * 32 + jj * 8 + j * 4;
                float4 m  = *(const float4*)(mean + kg);
                float4 is = *(const float4*)(invstd + kg);
                float vv[4] = {(v.x - m.x) * is.x, (v.y - m.y) * is.y,
                               (v.z - m.z) * is.z, (v.w - m.w) * is.w};
#pragma unroll
                for (int q = 0; q < 4; q++) {
                    __half h = __float2half_rn(vv[q]);
                    hi8[j * 4 + q] = h;
                    lo8[j * 4 + q] = __float2half_rn(vv[q] - __half2float(h));
                }
            }
            int off = arow * AL + ahalf * 32 + jj * 8;
            *(uint4*)&As_hi[off] = *(const uint4*)hi8;
            *(uint4*)&As_lo[off] = *(const uint4*)lo8;
        }
#pragma unroll
        for (int i = tid; i < 768; i += 256) {
            int r = i / 12, c8 = i % 12;
            size_t gsrc = (size_t)(kc + r) * HID + c8 * 8;
            int sdst = r * WL + c8 * 8;
            *(uint4*)&Ws_hi[sdst] = *(const uint4*)(Wh + gsrc);
            *(uint4*)&Ws_lo[sdst] = *(const uint4*)(Wl + gsrc);
        }
        __syncthreads();

        if (chunk == 0) {
            const float* Ap = A + (size_t)grow * IN_DIM + 64 + ahalf * 32;
#pragma unroll
            for (int j = 0; j < 8; j++)
                cur[j] = aok ? *(const float4*)(Ap + j * 4)
                             : make_float4(0.f, 0.f, 0.f, 0.f);
        }

        if (active) {
#pragma unroll
            for (int kk = 0; kk < 4; kk++) {
                wmma::fragment<wmma::matrix_a, 16, 16, 16, __half, wmma::row_major> fa_hi, fa_lo;
                wmma::load_matrix_sync(fa_hi, &As_hi[(w * 16) * AL + kk * 16], AL);
                wmma::load_matrix_sync(fa_lo, &As_lo[(w * 16) * AL + kk * 16], AL);
#pragma unroll
                for (int c = 0; c < 6; c++) {
                    wmma::fragment<wmma::matrix_b, 16, 16, 16, __half, wmma::row_major> fb_hi, fb_lo;
                    wmma::load_matrix_sync(fb_hi, &Ws_hi[(kk * 16) * WL + c * 16], WL);
                    wmma::load_matrix_sync(fb_lo, &Ws_lo[(kk * 16) * WL + c * 16], WL);
                    wmma::mma_sync(acc[c], fa_hi, fb_hi, acc[c]);
                    wmma::mma_sync(acc[c], fa_lo, fb_hi, acc[c]);
                    wmma::mma_sync(acc[c], fa_hi, fb_lo, acc[c]);
                }
            }
        }
        __syncthreads();
    }

    if (active) {
        wmma::fragment<wmma::accumulator, 16, 16, 16, __half> hacc;
#pragma unroll
        for (int c = 0; c < 6; c++) {
#pragma unroll
            for (int i = 0; i < hacc.num_elements; i++)
                hacc.x[i] = __float2half_rn(acc[c].x[i]);
            wmma::store_matrix_sync(out + (size_t)(row0 + w * 16) * HID + c * 16,
                                    hacc, HID, wmma::mem_row_major);
        }
    }
}

// ---------------------------------------------------------------------------
// GEMM2 (tensor, 2-pass): z2 = hh (fp16 exact) @ W2(hi+lo)
// ---------------------------------------------------------------------------
__global__ void __launch_bounds__(256)
k_gemm2(const __half* __restrict__ Ah,
        const __half* __restrict__ Wh, const __half* __restrict__ Wl,
        __half* __restrict__ out, int n)
{
    constexpr int AL = 104;
    constexpr int WL = 104;
    __shared__ __align__(16) __half As[128 * AL];
    __shared__ __align__(16) __half Ws_hi[96 * WL];
    __shared__ __align__(16) __half Ws_lo[96 * WL];

    const int tid = threadIdx.x, w = tid >> 5;
    const int row0 = blockIdx.x * 128;
    const bool active = (row0 + w * 16) < n;

#pragma unroll
    for (int i = tid; i < 1536; i += 256) {
        int r = i / 12, c8 = i % 12;
        int grow = row0 + r;
        uint4 v = (grow < n) ? *(const uint4*)(Ah + (size_t)grow * HID + c8 * 8)
                             : make_uint4(0, 0, 0, 0);
        *(uint4*)&As[r * AL + c8 * 8] = v;
    }
#pragma unroll
    for (int i = tid; i < 1152; i += 256) {
        int r = i / 12, c8 = i % 12;
        size_t gsrc = (size_t)r * HID + c8 * 8;
        int sdst = r * WL + c8 * 8;
        *(uint4*)&Ws_hi[sdst] = *(const uint4*)(Wh + gsrc);
        *(uint4*)&Ws_lo[sdst] = *(const uint4*)(Wl + gsrc);
    }
    __syncthreads();

    if (active) {
        wmma::fragment<wmma::accumulator, 16, 16, 16, float> acc[6];
#pragma unroll
        for (int c = 0; c < 6; c++) wmma::fill_fragment(acc[c], 0.0f);

#pragma unroll
        for (int kk = 0; kk < 6; kk++) {
            wmma::fragment<wmma::matrix_a, 16, 16, 16, __half, wmma::row_major> fa;
            wmma::load_matrix_sync(fa, &As[(w * 16) * AL + kk * 16], AL);
#pragma unroll
            for (int c = 0; c < 6; c++) {
                wmma::fragment<wmma::matrix_b, 16, 16, 16, __half, wmma::row_major> fb_hi, fb_lo;
                wmma::load_matrix_sync(fb_hi, &Ws_hi[(kk * 16) * WL + c * 16], WL);
                wmma::load_matrix_sync(fb_lo, &Ws_lo[(kk * 16) * WL + c * 16], WL);
                wmma::mma_sync(acc[c], fa, fb_hi, acc[c]);
                wmma::mma_sync(acc[c], fa, fb_lo, acc[c]);
            }
        }

        wmma::fragment<wmma::accumulator, 16, 16, 16, __half> hacc;
#pragma unroll
        for (int c = 0; c < 6; c++) {
#pragma unroll
            for (int i = 0; i < hacc.num_elements; i++)
                hacc.x[i] = __float2half_rn(acc[c].x[i]);
            wmma::store_matrix_sync(out + (size_t)(row0 + w * 16) * HID + c * 16,
                                    hacc, HID, wmma::mem_row_major);
        }
    }
}

// ---------------------------------------------------------------------------
// Gather helpers
// ---------------------------------------------------------------------------
__device__ __forceinline__ void fma_u4(float* acc, uint4 u, float ds) {
    __half2* hp = (__half2*)&u;
#pragma unroll
    for (int w = 0; w < 4; w++) {
        float2 f = __half22float2(hp[w]);
        acc[2 * w]     = fmaf(ds, f.x, acc[2 * w]);
        acc[2 * w + 1] = fmaf(ds, f.y, acc[2 * w + 1]);
    }
}
__device__ __forceinline__ void scale_u4(float* acc, uint4 u, float ds) {
    __half2* hp = (__half2*)&u;
#pragma unroll
    for (int w = 0; w < 4; w++) {
        float2 f = __half22float2(hp[w]);
        acc[2 * w]     = ds * f.x;
        acc[2 * w + 1] = ds * f.y;
    }
}
__device__ __forceinline__ void add_u4(float* acc, uint4 u) {
    __half2* hp = (__half2*)&u;
#pragma unroll
    for (int w = 0; w < 4; w++) {
        float2 f = __half22float2(hp[w]);
        acc[2 * w]     += f.x;
        acc[2 * w + 1] += f.y;
    }
}
__device__ __forceinline__ void init_u4(float* acc, uint4 u) {
    __half2* hp = (__half2*)&u;
#pragma unroll
    for (int w = 0; w < 4; w++) {
        float2 f = __half22float2(hp[w]);
        acc[2 * w]     = f.x;
        acc[2 * w + 1] = f.y;
    }
}

// Gather 1 (z has NO dinv), 4-wide unrolled (12 uint4 in flight):
// hh = dinv[v]*relu(dinv[v]*(dinv-weighted sum) + b1), fp16
__global__ void __launch_bounds__(256)
k_gather_br(const int* __restrict__ rowptr, const int* __restrict__ col,
            const float* __restrict__ dinv, const __half* __restrict__ z,
            const float* __restrict__ bias, __half* __restrict__ h, int n)
{
    int t = blockIdx.x * blockDim.x + threadIdx.x;
    int v = t >> 2, part = t & 3;
    if (v >= n) return;
    int beg = rowptr[v], end = rowptr[v + 1];
    float dv = dinv[v];
    float acc[24];
    {
        const uint4* self = (const uint4*)(z + (size_t)v * HID + part * 24);
        uint4 u0 = self[0], u1 = self[1], u2 = self[2];
        scale_u4(acc, u0, dv); scale_u4(acc + 8, u1, dv); scale_u4(acc + 16, u2, dv);
    }
    int j = beg;
    for (; j + 3 < end; j += 4) {
        int s0 = col[j], s1 = col[j + 1], s2 = col[j + 2], s3 = col[j + 3];
        float d0 = dinv[s0], d1 = dinv[s1], d2 = dinv[s2], d3 = dinv[s3];
        const uint4* p0 = (const uint4*)(z + (size_t)s0 * HID + part * 24);
        const uint4* p1 = (const uint4*)(z + (size_t)s1 * HID + part * 24);
        const uint4* p2 = (const uint4*)(z + (size_t)s2 * HID + part * 24);
        const uint4* p3 = (const uint4*)(z + (size_t)s3 * HID + part * 24);
        uint4 a0 = p0[0], a1 = p0[1], a2 = p0[2];
        uint4 b0 = p1[0], b1 = p1[1], b2 = p1[2];
        uint4 c0 = p2[0], c1 = p2[1], c2 = p2[2];
        uint4 e0 = p3[0], e1 = p3[1], e2 = p3[2];
        fma_u4(acc, a0, d0); fma_u4(acc + 8, a1, d0); fma_u4(acc + 16, a2, d0);
        fma_u4(acc, b0, d1); fma_u4(acc + 8, b1, d1); fma_u4(acc + 16, b2, d1);
        fma_u4(acc, c0, d2); fma_u4(acc + 8, c1, d2); fma_u4(acc + 16, c2, d2);
        fma_u4(acc, e0, d3); fma_u4(acc + 8, e1, d3); fma_u4(acc + 16, e2, d3);
    }
    for (; j < end; j++) {
        int s0 = col[j];
        float d0 = dinv[s0];
        const uint4* p0 = (const uint4*)(z + (size_t)s0 * HID + part * 24);
        uint4 a0 = p0[0], a1 = p0[1], a2 = p0[2];
        fma_u4(acc, a0, d0); fma_u4(acc + 8, a1, d0); fma_u4(acc + 16, a2, d0);
    }
    int kb = part * 24;
    __half o[24];
#pragma unroll
    for (int i = 0; i < 24; i++)
        o[i] = __float2half_rn(dv * fmaxf(fmaf(dv, acc[i], bias[kb + i]), 0.f));
    uint4* hp = (uint4*)(h + (size_t)v * HID + kb);
    hp[0] = *(const uint4*)&o[0];
    hp[1] = *(const uint4*)&o[8];
    hp[2] = *(const uint4*)&o[16];
}

// Gather 2 (z2 has per-row dinv folded), 4-wide unrolled:
// s[v] = dinv[v] * dot(relu(dinv[v]*acc + b2), w3v)
__global__ void __launch_bounds__(256)
k_gather_gemv(const int* __restrict__ rowptr, const int* __restrict__ col,
              const float* __restrict__ dinv, const __half* __restrict__ z,
              const float* __restrict__ bias, const float* __restrict__ w3v,
              float* __restrict__ s, int n)
{
    int t = blockIdx.x * blockDim.x + threadIdx.x;
    int v = t >> 2, part = t & 3;
    if (v >= n) return;
    int beg = rowptr[v], end = rowptr[v + 1];
    float acc[24];
    {
        const uint4* self = (const uint4*)(z + (size_t)v * HID + part * 24);
        uint4 u0 = self[0], u1 = self[1], u2 = self[2];
        init_u4(acc, u0); init_u4(acc + 8, u1); init_u4(acc + 16, u2);
    }
    int j = beg;
    for (; j + 3 < end; j += 4) {
        int s0 = col[j], s1 = col[j + 1], s2 = col[j + 2], s3 = col[j + 3];
        const uint4* p0 = (const uint4*)(z + (size_t)s0 * HID + part * 24);
        const uint4* p1 = (const uint4*)(z + (size_t)s1 * HID + part * 24);
        const uint4* p2 = (const uint4*)(z + (size_t)s2 * HID + part * 24);
        const uint4* p3 = (const uint4*)(z + (size_t)s3 * HID + part * 24);
        uint4 a0 = p0[0], a1 = p0[1], a2 = p0[2];
        uint4 b0 = p1[0], b1 = p1[1], b2 = p1[2];
        uint4 c0 = p2[0], c1 = p2[1], c2 = p2[2];
        uint4 e0 = p3[0], e1 = p3[1], e2 = p3[2];
        add_u4(acc, a0); add_u4(acc + 8, a1); add_u4(acc + 16, a2);
        add_u4(acc, b0); add_u4(acc + 8, b1); add_u4(acc + 16, b2);
        add_u4(acc, c0); add_u4(acc + 8, c1); add_u4(acc + 16, c2);
        add_u4(acc, e0); add_u4(acc + 8, e1); add_u4(acc + 16, e2);
    }
    for (; j < end; j++) {
        const uint4* p0 = (const uint4*)(z + (size_t)col[j] * HID + part * 24);
        uint4 a0 = p0[0], a1 = p0[1], a2 = p0[2];
        add_u4(acc, a0); add_u4(acc + 8, a1); add_u4(acc + 16, a2);
    }
    float dv = dinv[v];
    int kb = part * 24;
    float partial = 0.f;
#pragma unroll
    for (int i = 0; i < 24; i++) {
        float hv = fmaxf(fmaf(dv, acc[i], bias[kb + i]), 0.f);
        partial = fmaf(hv, w3v[kb + i], partial);
    }
    partial += __shfl_xor_sync(0xffffffffu, partial, 1);
    partial += __shfl_xor_sync(0xffffffffu, partial, 2);
    if (part == 0) s[v] = dv * partial;
}

// Final scalar prop
__global__ void __launch_bounds__(256)
k_out(const int* __restrict__ rowptr, const int* __restrict__ col,
      const float* __restrict__ dinv, const float* __restrict__ s,
      const float* __restrict__ w3v, float* __restrict__ out, int n)
{
    int t = blockIdx.x * blockDim.x + threadIdx.x;
    int v = t >> 3, part = t & 7;
    if (v >= n) return;
    int beg = rowptr[v], end = rowptr[v + 1];
    float acc = 0.f;
    for (int j = beg + part; j < end; j += 8)
        acc += s[col[j]];
    acc += __shfl_xor_sync(0xffffffffu, acc, 4);
    acc += __shfl_xor_sync(0xffffffffu, acc, 2);
    acc += __shfl_xor_sync(0xffffffffu, acc, 1);
    if (part == 0) out[v] = fmaf(dinv[v], acc + s[v], w3v[HID]);
}

// ---------------------------------------------------------------------------
// Host launch: fork GEMM1 vs CSR build; split tail.
// ---------------------------------------------------------------------------
extern "C" void kernel_launch(void* const* d_in, const int* in_sizes, int n_in,
                              void* d_out, int out_size)
{
    const float* x    = (const float*)d_in[0];
    const int*   ei   = (const int*)d_in[1];
    // d_in[2] = PQVA_mask (deterministic: output = column 1)
    const float* mean = (const float*)d_in[3];
    const float* stdv = (const float*)d_in[4];
    const float* W1   = (const float*)d_in[5];
    const float* b1   = (const float*)d_in[6];
    const float* W2   = (const float*)d_in[7];
    const float* b2   = (const float*)d_in[8];
    const float* W3   = (const float*)d_in[9];
    const float* b3   = (const float*)d_in[10];
    const float* Wout = (const float*)d_in[11];
    const float* bout = (const float*)d_in[12];
    float* out = (float*)d_out;

    const int N = in_sizes[0] / IN_DIM;
    const int E = in_sizes[1] / 2;

    __half *zh, *hh, *w1h, *w1l, *w2h, *w2l;
    float *sv, *dinv, *invstd, *w3v;
    int *cnt, *rowptr, *cursor, *colb, *bval, *bflag;
    cudaGetSymbolAddress((void**)&zh, g_zh);
    cudaGetSymbolAddress((void**)&hh, g_hh);
    cudaGetSymbolAddress((void**)&w1h, g_w1h);
    cudaGetSymbolAddress((void**)&w1l, g_w1l);
    cudaGetSymbolAddress((void**)&w2h, g_w2h);
    cudaGetSymbolAddress((void**)&w2l, g_w2l);
    cudaGetSymbolAddress((void**)&sv, g_s);
    cudaGetSymbolAddress((void**)&dinv, g_dinv);
    cudaGetSymbolAddress((void**)&invstd, g_invstd);
    cudaGetSymbolAddress((void**)&w3v, g_w3v);
    cudaGetSymbolAddress((void**)&cnt, g_cnt);
    cudaGetSymbolAddress((void**)&rowptr, g_rowptr);
    cudaGetSymbolAddress((void**)&cursor, g_cursor);
    cudaGetSymbolAddress((void**)&colb, g_col);
    cudaGetSymbolAddress((void**)&bval, g_bval);
    cudaGetSymbolAddress((void**)&bflag, g_bflag);

    const int TB = 256;
    int nb_n = (N + TB - 1) / TB;
    int nb_e2 = (E / 2 + TB - 1) / TB + 1;
    int nb_gemm = (N + 127) / 128;
    int nb_g4 = (N * 4 + TB - 1) / TB;
    int nb_g8 = (N * 8 + TB - 1) / TB;
    int nb_scan = (N + SCAN_CH - 1) / SCAN_CH;

    cudaStream_t s2;
    cudaStreamCreateWithFlags(&s2, cudaStreamNonBlocking);
    cudaEvent_t eFork, eJoin;
    cudaEventCreateWithFlags(&eFork, cudaEventDisableTiming);
    cudaEventCreateWithFlags(&eJoin, cudaEventDisableTiming);

    k_pre<<<nb_n, TB>>>(cnt, N, bflag, stdv, invstd, W1, W2, W3, b3,
                        Wout, bout, w3v, w1h, w1l, w2h, w2l);
    cudaEventRecord(eFork, 0);
    cudaStreamWaitEvent(s2, eFork, 0);

    // Branch A (side stream): GEMM1
    k_gemm1<<<nb_gemm, TB, 0, s2>>>(x, w1h, w1l, mean, invstd, zh, N);
    cudaEventRecord(eJoin, s2);

    // Branch B (main stream): CSR build
    k_count<<<nb_e2, TB>>>(ei, E, cnt);
    k_scan<<<nb_scan, TB>>>(cnt, N, rowptr, cursor, dinv, bval, bflag);
    k_fill<<<nb_e2, TB>>>(ei, E, cursor, colb);

    cudaStreamWaitEvent(0, eJoin, 0);

    // Tail
    k_gather_br<<<nb_g4, TB>>>(rowptr, colb, dinv, zh, b1, hh, N);
    k_gemm2<<<nb_gemm, TB>>>(hh, w2h, w2l, zh, N);
    k_gather_gemv<<<nb_g4, TB>>>(rowptr, colb, dinv, zh, b2, w3v, sv, N);
    k_out<<<nb_g8, TB>>>(rowptr, colb, dinv, sv, w3v, out, N);
}

// round 16
// speedup vs baseline: 1.1037x; 1.1037x over previous
#include <cuda_runtime.h>
#include <cuda_fp16.h>
#include <mma.h>
#include <cstdint>

using namespace nvcuda;

#define MAXN 50000
#define IN_DIM 128
#define HID 96
#define EMAX 1048576
#define SCAN_CH 512
#define SCAN_MAXB 128

// Static scratch (no runtime allocation allowed)
__device__ __align__(16) __half g_zh[MAXN * HID];  // GEMM outputs (fp16)
__device__ __align__(16) __half g_hh[MAXN * HID];  // gather outputs (dinv*relu, fp16)
__device__ __align__(16) __half g_w1h[IN_DIM * HID];
__device__ __align__(16) __half g_w1l[IN_DIM * HID];
__device__ __align__(16) __half g_w2h[HID * HID];
__device__ __align__(16) __half g_w2l[HID * HID];
__device__ float g_s[MAXN];
__device__ float g_dinv[MAXN];
__device__ float g_invstd[IN_DIM];
__device__ float g_w3v[HID + 1];
__device__ int   g_cnt[MAXN];
__device__ int   g_rowptr[MAXN + 1];
__device__ int   g_cursor[MAXN];
__device__ int   g_bval[SCAN_MAXB];
__device__ int   g_bflag[SCAN_MAXB];
__device__ int   g_col[EMAX];

// ---------------------------------------------------------------------------
// Pre: zero cnt/flags, invstd, w3v, W1/W2 hi-lo conversion (one launch)
// ---------------------------------------------------------------------------
__global__ void __launch_bounds__(256)
k_pre(int* cnt, int n, int* bflag,
      const float* __restrict__ stdv, float* __restrict__ invstd,
      const float* __restrict__ W1, const float* __restrict__ W2,
      const float* __restrict__ W3, const float* __restrict__ b3,
      const float* __restrict__ Wout, const float* __restrict__ bout,
      float* __restrict__ w3v,
      __half* __restrict__ w1h, __half* __restrict__ w1l,
      __half* __restrict__ w2h, __half* __restrict__ w2l)
{
    int b = blockIdx.x, tid = threadIdx.x;
    int i = b * 256 + tid;
    if (i < n) cnt[i] = 0;
    if (b == 0 && tid < SCAN_MAXB) bflag[tid] = 0;
    if (b == 1 && tid < IN_DIM) invstd[tid] = 1.0f / stdv[tid];
    if (b == 2 || b == 3) {
        __shared__ float swout[HID];
        if (tid < HID) swout[tid] = Wout[2 * tid + 1];
        __syncthreads();
        int rl = tid >> 2, q = tid & 3;
        int r = (b - 2) * 48 + (rl < 48 ? rl : 47);
        float a = 0.f;
#pragma unroll 8
        for (int j = q * 24; j < q * 24 + 24; j++)
            a = fmaf(W3[r * HID + j], swout[j], a);
        a += __shfl_xor_sync(~0u, a, 1);
        a += __shfl_xor_sync(~0u, a, 2);
        if (q == 0 && rl < 48) w3v[r] = a;
        if (b == 2 && tid == 255) {
            float c = bout[1];
#pragma unroll 8
            for (int j = 0; j < HID; j++) c = fmaf(b3[j], swout[j], c);
            w3v[HID] = c;
        }
    }
    if (b >= 4 && b < 52) {
        int j = (b - 4) * 256 + tid;
        float wv = W1[j];
        __half h = __float2half_rn(wv);
        w1h[j] = h;
        w1l[j] = __float2half_rn(wv - __half2float(h));
    }
    if (b >= 52 && b < 88) {
        int j = (b - 52) * 256 + tid;
        float wv = W2[j];
        __half h = __float2half_rn(wv);
        w2h[j] = h;
        w2l[j] = __float2half_rn(wv - __half2float(h));
    }
}

__global__ void k_count(const int* __restrict__ ei, int E, int* cnt) {
    int e = blockIdx.x * blockDim.x + threadIdx.x;
    if (e < E) atomicAdd(&cnt[ei[E + e]], 1);
}

// ---------------------------------------------------------------------------
// Single-kernel scan (decoupled lookback)
// ---------------------------------------------------------------------------
__global__ void __launch_bounds__(256)
k_scan(const int* __restrict__ cnt, int n, int* __restrict__ rowptr,
       int* __restrict__ cursor, float* __restrict__ dinv,
       int* bval, int* bflag)
{
    __shared__ int wsum[8];
    __shared__ int s_base;
    int b = blockIdx.x, tid = threadIdx.x, lane = tid & 31, wid = tid >> 5;
    int i0 = b * SCAN_CH + 2 * tid;
    int c0 = (i0     < n) ? cnt[i0]     : 0;
    int c1 = (i0 + 1 < n) ? cnt[i0 + 1] : 0;
    int s = c0 + c1;
    int x = s;
#pragma unroll
    for (int d = 1; d < 32; d <<= 1) {
        int t = __shfl_up_sync(~0u, x, d);
        if (lane >= d) x += t;
    }
    if (lane == 31) wsum[wid] = x;
    __syncthreads();
    if (wid == 0 && lane < 8) {
        int ws = wsum[lane];
#pragma unroll
        for (int d = 1; d < 8; d <<= 1) {
            int t = __shfl_up_sync(0xFF, ws, d);
            if (lane >= d) ws += t;
        }
        wsum[lane] = ws;
    }
    __syncthreads();
    int ex_local = x - s + (wid ? wsum[wid - 1] : 0);
    int block_total = wsum[7];

    if (tid == 0) {
        atomicExch(&bval[b], block_total);
        __threadfence();
        atomicExch(&bflag[b], 1);
        if (b == 0) rowptr[0] = 0;
    }
    if (wid == 0) {
        int part = 0;
        for (int j = lane; j < b; j += 32) {
            while (atomicAdd(&bflag[j], 0) == 0) {}
            part += atomicAdd(&bval[j], 0);
        }
#pragma unroll
        for (int d = 16; d; d >>= 1) part += __shfl_xor_sync(~0u, part, d);
        if (lane == 0) s_base = part;
    }
    __syncthreads();
    int ex = ex_local + s_base;
    if (i0 < n) {
        cursor[i0]     = ex;
        rowptr[i0 + 1] = ex + c0;
        dinv[i0]       = rsqrtf((float)(c0 + 1));
    }
    if (i0 + 1 < n) {
        cursor[i0 + 1] = ex + c0;
        rowptr[i0 + 2] = ex + c0 + c1;
        dinv[i0 + 1]   = rsqrtf((float)(c1 + 1));
    }
}

__global__ void k_fill(const int* __restrict__ ei, int E,
                       int* __restrict__ cursor, int* __restrict__ col)
{
    int e = blockIdx.x * blockDim.x + threadIdx.x;
    if (e >= E) return;
    int s = ei[e], d = ei[E + e];
    int slot = atomicAdd(&cursor[d], 1);
    col[slot] = s;
}

// ---------------------------------------------------------------------------
// GEMM1 (tensor, 3-pass hi/lo): z = scaler(x) @ W1  (no dinv)
// minBlocksPerMultiprocessor=3 forces regs<=85 -> 3 blocks/SM (occupancy for
// the DRAM x-stream, which bounds this kernel).
// ---------------------------------------------------------------------------
__global__ void __launch_bounds__(256, 3)
k_gemm1(const float* __restrict__ A,
        const __half* __restrict__ Wh, const __half* __restrict__ Wl,
        const float* __restrict__ mean, const float* __restrict__ invstd,
        __half* __restrict__ out, int n)
{
    constexpr int AL = 72;
    constexpr int WL = 104;
    __shared__ __align__(16) __half As_hi[128 * AL];
    __shared__ __align__(16) __half As_lo[128 * AL];
    __shared__ __align__(16) __half Ws_hi[64 * WL];
    __shared__ __align__(16) __half Ws_lo[64 * WL];

    const int tid = threadIdx.x, w = tid >> 5;
    const int row0 = blockIdx.x * 128;
    const int arow = tid >> 1, ahalf = tid & 1;
    const int grow = row0 + arow;
    const bool aok = grow < n;
    const bool active = (row0 + w * 16) < n;

    wmma::fragment<wmma::accumulator, 16, 16, 16, float> acc[6];
#pragma unroll
    for (int c = 0; c < 6; c++) wmma::fill_fragment(acc[c], 0.0f);

#pragma unroll 1
    for (int kc = 0; kc < IN_DIM; kc += 64) {
        const float* Ap = A + (size_t)grow * IN_DIM + kc + ahalf * 32;
#pragma unroll
        for (int jj = 0; jj < 4; jj++) {
            __half hi8[8], lo8[8];
#pragma unroll
            for (int j = 0; j < 2; j++) {
                float4 v = aok ? *(const float4*)(Ap + jj * 8 + j * 4)
                               : make_float4(0.f, 0.f, 0.f, 0.f);
                int kg = kc + ahalf * 32 + jj * 8 + j * 4;
                float4 m  = *(const float4*)(mean + kg);
                float4 is = *(const float4*)(invstd + kg);
                float vv[4] = {(v.x - m.x) * is.x, (v.y - m.y) * is.y,
                               (v.z - m.z) * is.z, (v.w - m.w) * is.w};
#pragma unroll
                for (int q = 0; q < 4; q++) {
                    __half h = __float2half_rn(vv[q]);
                    hi8[j * 4 + q] = h;
                    lo8[j * 4 + q] = __float2half_rn(vv[q] - __half2float(h));
                }
            }
            int off = arow * AL + ahalf * 32 + jj * 8;
            *(uint4*)&As_hi[off] = *(const uint4*)hi8;
            *(uint4*)&As_lo[off] = *(const uint4*)lo8;
        }
#pragma unroll
        for (int i = tid; i < 768; i += 256) {
            int r = i / 12, c8 = i % 12;
            size_t gsrc = (size_t)(kc + r) * HID + c8 * 8;
            int sdst = r * WL + c8 * 8;
            *(uint4*)&Ws_hi[sdst] = *(const uint4*)(Wh + gsrc);
            *(uint4*)&Ws_lo[sdst] = *(const uint4*)(Wl + gsrc);
        }
        __syncthreads();

        if (active) {
#pragma unroll
            for (int kk = 0; kk < 4; kk++) {
                wmma::fragment<wmma::matrix_a, 16, 16, 16, __half, wmma::row_major> fa_hi, fa_lo;
                wmma::load_matrix_sync(fa_hi, &As_hi[(w * 16) * AL + kk * 16], AL);
                wmma::load_matrix_sync(fa_lo, &As_lo[(w * 16) * AL + kk * 16], AL);
#pragma unroll
                for (int c = 0; c < 6; c++) {
                    wmma::fragment<wmma::matrix_b, 16, 16, 16, __half, wmma::row_major> fb_hi, fb_lo;
                    wmma::load_matrix_sync(fb_hi, &Ws_hi[(kk * 16) * WL + c * 16], WL);
                    wmma::load_matrix_sync(fb_lo, &Ws_lo[(kk * 16) * WL + c * 16], WL);
                    wmma::mma_sync(acc[c], fa_hi, fb_hi, acc[c]);
                    wmma::mma_sync(acc[c], fa_lo, fb_hi, acc[c]);
                    wmma::mma_sync(acc[c], fa_hi, fb_lo, acc[c]);
                }
            }
        }
        __syncthreads();
    }

    if (active) {
        wmma::fragment<wmma::accumulator, 16, 16, 16, __half> hacc;
#pragma unroll
        for (int c = 0; c < 6; c++) {
#pragma unroll
            for (int i = 0; i < hacc.num_elements; i++)
                hacc.x[i] = __float2half_rn(acc[c].x[i]);
            wmma::store_matrix_sync(out + (size_t)(row0 + w * 16) * HID + c * 16,
                                    hacc, HID, wmma::mem_row_major);
        }
    }
}

// ---------------------------------------------------------------------------
// GEMM2 (tensor, 2-pass): z2 = hh (fp16 exact) @ W2(hi+lo)
// ---------------------------------------------------------------------------
__global__ void __launch_bounds__(256)
k_gemm2(const __half* __restrict__ Ah,
        const __half* __restrict__ Wh, const __half* __restrict__ Wl,
        __half* __restrict__ out, int n)
{
    constexpr int AL = 104;
    constexpr int WL = 104;
    __shared__ __align__(16) __half As[128 * AL];
    __shared__ __align__(16) __half Ws_hi[96 * WL];
    __shared__ __align__(16) __half Ws_lo[96 * WL];

    const int tid = threadIdx.x, w = tid >> 5;
    const int row0 = blockIdx.x * 128;
    const bool active = (row0 + w * 16) < n;

#pragma unroll
    for (int i = tid; i < 1536; i += 256) {
        int r = i / 12, c8 = i % 12;
        int grow = row0 + r;
        uint4 v = (grow < n) ? *(const uint4*)(Ah + (size_t)grow * HID + c8 * 8)
                             : make_uint4(0, 0, 0, 0);
        *(uint4*)&As[r * AL + c8 * 8] = v;
    }
#pragma unroll
    for (int i = tid; i < 1152; i += 256) {
        int r = i / 12, c8 = i % 12;
        size_t gsrc = (size_t)r * HID + c8 * 8;
        int sdst = r * WL + c8 * 8;
        *(uint4*)&Ws_hi[sdst] = *(const uint4*)(Wh + gsrc);
        *(uint4*)&Ws_lo[sdst] = *(const uint4*)(Wl + gsrc);
    }
    __syncthreads();

    if (active) {
        wmma::fragment<wmma::accumulator, 16, 16, 16, float> acc[6];
#pragma unroll
        for (int c = 0; c < 6; c++) wmma::fill_fragment(acc[c], 0.0f);

#pragma unroll
        for (int kk = 0; kk < 6; kk++) {
            wmma::fragment<wmma::matrix_a, 16, 16, 16, __half, wmma::row_major> fa;
            wmma::load_matrix_sync(fa, &As[(w * 16) * AL + kk * 16], AL);
#pragma unroll
            for (int c = 0; c < 6; c++) {
                wmma::fragment<wmma::matrix_b, 16, 16, 16, __half, wmma::row_major> fb_hi, fb_lo;
                wmma::load_matrix_sync(fb_hi, &Ws_hi[(kk * 16) * WL + c * 16], WL);
                wmma::load_matrix_sync(fb_lo, &Ws_lo[(kk * 16) * WL + c * 16], WL);
                wmma::mma_sync(acc[c], fa, fb_hi, acc[c]);
                wmma::mma_sync(acc[c], fa, fb_lo, acc[c]);
            }
        }

        wmma::fragment<wmma::accumulator, 16, 16, 16, __half> hacc;
#pragma unroll
        for (int c = 0; c < 6; c++) {
#pragma unroll
            for (int i = 0; i < hacc.num_elements; i++)
                hacc.x[i] = __float2half_rn(acc[c].x[i]);
            wmma::store_matrix_sync(out + (size_t)(row0 + w * 16) * HID + c * 16,
                                    hacc, HID, wmma::mem_row_major);
        }
    }
}

// ---------------------------------------------------------------------------
// Gather helpers
// ---------------------------------------------------------------------------
__device__ __forceinline__ void fma_u4(float* acc, uint4 u, float ds) {
    __half2* hp = (__half2*)&u;
#pragma unroll
    for (int w = 0; w < 4; w++) {
        float2 f = __half22float2(hp[w]);
        acc[2 * w]     = fmaf(ds, f.x, acc[2 * w]);
        acc[2 * w + 1] = fmaf(ds, f.y, acc[2 * w + 1]);
    }
}
__device__ __forceinline__ void scale_u4(float* acc, uint4 u, float ds) {
    __half2* hp = (__half2*)&u;
#pragma unroll
    for (int w = 0; w < 4; w++) {
        float2 f = __half22float2(hp[w]);
        acc[2 * w]     = ds * f.x;
        acc[2 * w + 1] = ds * f.y;
    }
}
__device__ __forceinline__ void add_u4(float* acc, uint4 u) {
    __half2* hp = (__half2*)&u;
#pragma unroll
    for (int w = 0; w < 4; w++) {
        float2 f = __half22float2(hp[w]);
        acc[2 * w]     += f.x;
        acc[2 * w + 1] += f.y;
    }
}
__device__ __forceinline__ void init_u4(float* acc, uint4 u) {
    __half2* hp = (__half2*)&u;
#pragma unroll
    for (int w = 0; w < 4; w++) {
        float2 f = __half22float2(hp[w]);
        acc[2 * w]     = f.x;
        acc[2 * w + 1] = f.y;
    }
}

// Gather 1 (z has NO dinv): acc = dinv[v]*z[v] + sum dinv[s]*z[s];
// hh = dinv[v]*relu(dinv[v]*acc + b1), fp16.
__global__ void __launch_bounds__(256)
k_gather_br(const int* __restrict__ rowptr, const int* __restrict__ col,
            const float* __restrict__ dinv, const __half* __restrict__ z,
            const float* __restrict__ bias, __half* __restrict__ h, int n)
{
    int t = blockIdx.x * blockDim.x + threadIdx.x;
    int v = t >> 2, part = t & 3;
    if (v >= n) return;
    int beg = rowptr[v], end = rowptr[v + 1];
    float dv = dinv[v];
    float acc[24];
    {
        const uint4* self = (const uint4*)(z + (size_t)v * HID + part * 24);
        uint4 u0 = self[0], u1 = self[1], u2 = self[2];
        scale_u4(acc, u0, dv); scale_u4(acc + 8, u1, dv); scale_u4(acc + 16, u2, dv);
    }
    int j = beg;
    for (; j + 1 < end; j += 2) {
        int s0 = col[j], s1 = col[j + 1];
        float d0 = dinv[s0], d1 = dinv[s1];
        const uint4* p0 = (const uint4*)(z + (size_t)s0 * HID + part * 24);
        const uint4* p1 = (const uint4*)(z + (size_t)s1 * HID + part * 24);
        uint4 a0 = p0[0], a1 = p0[1], a2 = p0[2];
        uint4 b0 = p1[0], b1 = p1[1], b2 = p1[2];
        fma_u4(acc, a0, d0); fma_u4(acc + 8, a1, d0); fma_u4(acc + 16, a2, d0);
        fma_u4(acc, b0, d1); fma_u4(acc + 8, b1, d1); fma_u4(acc + 16, b2, d1);
    }
    if (j < end) {
        int s0 = col[j];
        float d0 = dinv[s0];
        const uint4* p0 = (const uint4*)(z + (size_t)s0 * HID + part * 24);
        uint4 a0 = p0[0], a1 = p0[1], a2 = p0[2];
        fma_u4(acc, a0, d0); fma_u4(acc + 8, a1, d0); fma_u4(acc + 16, a2, d0);
    }
    int kb = part * 24;
    __half o[24];
#pragma unroll
    for (int i = 0; i < 24; i++)
        o[i] = __float2half_rn(dv * fmaxf(fmaf(dv, acc[i], bias[kb + i]), 0.f));
    uint4* hp = (uint4*)(h + (size_t)v * HID + kb);
    hp[0] = *(const uint4*)&o[0];
    hp[1] = *(const uint4*)&o[8];
    hp[2] = *(const uint4*)&o[16];
}

// Gather 2 (z2 has per-row dinv folded): plain sum,
// s[v] = dinv[v] * dot(relu(dinv[v]*acc + b2), w3v)
__global__ void __launch_bounds__(256)
k_gather_gemv(const int* __restrict__ rowptr, const int* __restrict__ col,
              const float* __restrict__ dinv, const __half* __restrict__ z,
              const float* __restrict__ bias, const float* __restrict__ w3v,
              float* __restrict__ s, int n)
{
    int t = blockIdx.x * blockDim.x + threadIdx.x;
    int v = t >> 2, part = t & 3;
    if (v >= n) return;
    int beg = rowptr[v], end = rowptr[v + 1];
    float acc[24];
    {
        const uint4* self = (const uint4*)(z + (size_t)v * HID + part * 24);
        uint4 u0 = self[0], u1 = self[1], u2 = self[2];
        init_u4(acc, u0); init_u4(acc + 8, u1); init_u4(acc + 16, u2);
    }
    int j = beg;
    for (; j + 1 < end; j += 2) {
        int s0 = col[j], s1 = col[j + 1];
        const uint4* p0 = (const uint4*)(z + (size_t)s0 * HID + part * 24);
        const uint4* p1 = (const uint4*)(z + (size_t)s1 * HID + part * 24);
        uint4 a0 = p0[0], a1 = p0[1], a2 = p0[2];
        uint4 b0 = p1[0], b1 = p1[1], b2 = p1[2];
        add_u4(acc, a0); add_u4(acc + 8, a1); add_u4(acc + 16, a2);
        add_u4(acc, b0); add_u4(acc + 8, b1); add_u4(acc + 16, b2);
    }
    if (j < end) {
        const uint4* p0 = (const uint4*)(z + (size_t)col[j] * HID + part * 24);
        uint4 a0 = p0[0], a1 = p0[1], a2 = p0[2];
        add_u4(acc, a0); add_u4(acc + 8, a1); add_u4(acc + 16, a2);
    }
    float dv = dinv[v];
    int kb = part * 24;
    float partial = 0.f;
#pragma unroll
    for (int i = 0; i < 24; i++) {
        float hv = fmaxf(fmaf(dv, acc[i], bias[kb + i]), 0.f);
        partial = fmaf(hv, w3v[kb + i], partial);
    }
    partial += __shfl_xor_sync(0xffffffffu, partial, 1);
    partial += __shfl_xor_sync(0xffffffffu, partial, 2);
    if (part == 0) s[v] = dv * partial;
}

// Final scalar prop
__global__ void __launch_bounds__(256)
k_out(const int* __restrict__ rowptr, const int* __restrict__ col,
      const float* __restrict__ dinv, const float* __restrict__ s,
      const float* __restrict__ w3v, float* __restrict__ out, int n)
{
    int t = blockIdx.x * blockDim.x + threadIdx.x;
    int v = t >> 3, part = t & 7;
    if (v >= n) return;
    int beg = rowptr[v], end = rowptr[v + 1];
    float acc = 0.f;
    for (int j = beg + part; j < end; j += 8)
        acc += s[col[j]];
    acc += __shfl_xor_sync(0xffffffffu, acc, 4);
    acc += __shfl_xor_sync(0xffffffffu, acc, 2);
    acc += __shfl_xor_sync(0xffffffffu, acc, 1);
    if (part == 0) out[v] = fmaf(dinv[v], acc + s[v], w3v[HID]);
}

// ---------------------------------------------------------------------------
// Host launch: fork GEMM1 vs CSR build; split tail.
// ---------------------------------------------------------------------------
extern "C" void kernel_launch(void* const* d_in, const int* in_sizes, int n_in,
                              void* d_out, int out_size)
{
    const float* x    = (const float*)d_in[0];
    const int*   ei   = (const int*)d_in[1];
    // d_in[2] = PQVA_mask (deterministic: output = column 1)
    const float* mean = (const float*)d_in[3];
    const float* stdv = (const float*)d_in[4];
    const float* W1   = (const float*)d_in[5];
    const float* b1   = (const float*)d_in[6];
    const float* W2   = (const float*)d_in[7];
    const float* b2   = (const float*)d_in[8];
    const float* W3   = (const float*)d_in[9];
    const float* b3   = (const float*)d_in[10];
    const float* Wout = (const float*)d_in[11];
    const float* bout = (const float*)d_in[12];
    float* out = (float*)d_out;

    const int N = in_sizes[0] / IN_DIM;
    const int E = in_sizes[1] / 2;

    __half *zh, *hh, *w1h, *w1l, *w2h, *w2l;
    float *sv, *dinv, *invstd, *w3v;
    int *cnt, *rowptr, *cursor, *colb, *bval, *bflag;
    cudaGetSymbolAddress((void**)&zh, g_zh);
    cudaGetSymbolAddress((void**)&hh, g_hh);
    cudaGetSymbolAddress((void**)&w1h, g_w1h);
    cudaGetSymbolAddress((void**)&w1l, g_w1l);
    cudaGetSymbolAddress((void**)&w2h, g_w2h);
    cudaGetSymbolAddress((void**)&w2l, g_w2l);
    cudaGetSymbolAddress((void**)&sv, g_s);
    cudaGetSymbolAddress((void**)&dinv, g_dinv);
    cudaGetSymbolAddress((void**)&invstd, g_invstd);
    cudaGetSymbolAddress((void**)&w3v, g_w3v);
    cudaGetSymbolAddress((void**)&cnt, g_cnt);
    cudaGetSymbolAddress((void**)&rowptr, g_rowptr);
    cudaGetSymbolAddress((void**)&cursor, g_cursor);
    cudaGetSymbolAddress((void**)&colb, g_col);
    cudaGetSymbolAddress((void**)&bval, g_bval);
    cudaGetSymbolAddress((void**)&bflag, g_bflag);

    const int TB = 256;
    int nb_n = (N + TB - 1) / TB;
    int nb_e = (E + TB - 1) / TB;
    int nb_gemm = (N + 127) / 128;
    int nb_g4 = (N * 4 + TB - 1) / TB;
    int nb_g8 = (N * 8 + TB - 1) / TB;
    int nb_scan = (N + SCAN_CH - 1) / SCAN_CH;

    cudaStream_t s2;
    cudaStreamCreateWithFlags(&s2, cudaStreamNonBlocking);
    cudaEvent_t eFork, eJoin;
    cudaEventCreateWithFlags(&eFork, cudaEventDisableTiming);
    cudaEventCreateWithFlags(&eJoin, cudaEventDisableTiming);

    k_pre<<<nb_n, TB>>>(cnt, N, bflag, stdv, invstd, W1, W2, W3, b3,
                        Wout, bout, w3v, w1h, w1l, w2h, w2l);
    cudaEventRecord(eFork, 0);
    cudaStreamWaitEvent(s2, eFork, 0);

    // Branch A (side stream): GEMM1
    k_gemm1<<<nb_gemm, TB, 0, s2>>>(x, w1h, w1l, mean, invstd, zh, N);
    cudaEventRecord(eJoin, s2);

    // Branch B (main stream): CSR build
    k_count<<<nb_e, TB>>>(ei, E, cnt);
    k_scan<<<nb_scan, TB>>>(cnt, N, rowptr, cursor, dinv, bval, bflag);
    k_fill<<<nb_e, TB>>>(ei, E, cursor, colb);

    cudaStreamWaitEvent(0, eJoin, 0);

    // Tail
    k_gather_br<<<nb_g4, TB>>>(rowptr, colb, dinv, zh, b1, hh, N);
    k_gemm2<<<nb_gemm, TB>>>(hh, w2h, w2l, zh, N);
    k_gather_gemv<<<nb_g4, TB>>>(rowptr, colb, dinv, zh, b2, w3v, sv, N);
    k_out<<<nb_g8, TB>>>(rowptr, colb, dinv, sv, w3v, out, N);
}

// round 17
// speedup vs baseline: 1.1044x; 1.0006x over previous
#include <cuda_runtime.h>
#include <cuda_fp16.h>
#include <mma.h>
#include <cstdint>

using namespace nvcuda;

#define MAXN 50000
#define IN_DIM 128
#define HID 96
#define EMAX 1048576
#define SCAN_CH 512
#define SCAN_MAXB 128

// Static scratch (no runtime allocation allowed)
__device__ __align__(16) __half g_zh[MAXN * HID];  // GEMM outputs (fp16)
__device__ __align__(16) __half g_hh[MAXN * HID];  // gather outputs (dinv*relu, fp16)
__device__ __align__(16) __half g_w1h[IN_DIM * HID];
__device__ __align__(16) __half g_w1l[IN_DIM * HID];
__device__ __align__(16) __half g_w2h[HID * HID];
__device__ __align__(16) __half g_w2l[HID * HID];
__device__ float g_s[MAXN];
__device__ float g_dinv[MAXN];
__device__ float g_invstd[IN_DIM];
__device__ float g_w3v[HID + 1];
__device__ int   g_cnt[MAXN];
__device__ int   g_rowptr[MAXN + 1];
__device__ int   g_cursor[MAXN];
__device__ int   g_bval[SCAN_MAXB];
__device__ int   g_bflag[SCAN_MAXB];
__device__ int   g_col[EMAX];

// ---------------------------------------------------------------------------
// Pre: zero cnt/flags, invstd, w3v, W1/W2 hi-lo conversion (one launch)
// ---------------------------------------------------------------------------
__global__ void __launch_bounds__(256)
k_pre(int* cnt, int n, int* bflag,
      const float* __restrict__ stdv, float* __restrict__ invstd,
      const float* __restrict__ W1, const float* __restrict__ W2,
      const float* __restrict__ W3, const float* __restrict__ b3,
      const float* __restrict__ Wout, const float* __restrict__ bout,
      float* __restrict__ w3v,
      __half* __restrict__ w1h, __half* __restrict__ w1l,
      __half* __restrict__ w2h, __half* __restrict__ w2l)
{
    int b = blockIdx.x, tid = threadIdx.x;
    int i = b * 256 + tid;
    if (i < n) cnt[i] = 0;
    if (b == 0 && tid < SCAN_MAXB) bflag[tid] = 0;
    if (b == 1 && tid < IN_DIM) invstd[tid] = 1.0f / stdv[tid];
    if (b == 2 || b == 3) {
        __shared__ float swout[HID];
        if (tid < HID) swout[tid] = Wout[2 * tid + 1];
        __syncthreads();
        int rl = tid >> 2, q = tid & 3;
        int r = (b - 2) * 48 + (rl < 48 ? rl : 47);
        float a = 0.f;
#pragma unroll 8
        for (int j = q * 24; j < q * 24 + 24; j++)
            a = fmaf(W3[r * HID + j], swout[j], a);
        a += __shfl_xor_sync(~0u, a, 1);
        a += __shfl_xor_sync(~0u, a, 2);
        if (q == 0 && rl < 48) w3v[r] = a;
        if (b == 2 && tid == 255) {
            float c = bout[1];
#pragma unroll 8
            for (int j = 0; j < HID; j++) c = fmaf(b3[j], swout[j], c);
            w3v[HID] = c;
        }
    }
    if (b >= 4 && b < 52) {
        int j = (b - 4) * 256 + tid;
        float wv = W1[j];
        __half h = __float2half_rn(wv);
        w1h[j] = h;
        w1l[j] = __float2half_rn(wv - __half2float(h));
    }
    if (b >= 52 && b < 88) {
        int j = (b - 52) * 256 + tid;
        float wv = W2[j];
        __half h = __float2half_rn(wv);
        w2h[j] = h;
        w2l[j] = __float2half_rn(wv - __half2float(h));
    }
}

__global__ void k_count(const int* __restrict__ ei, int E, int* cnt) {
    int e = blockIdx.x * blockDim.x + threadIdx.x;
    if (e < E) atomicAdd(&cnt[ei[E + e]], 1);
}

// ---------------------------------------------------------------------------
// Single-kernel scan (decoupled lookback)
// ---------------------------------------------------------------------------
__global__ void __launch_bounds__(256)
k_scan(const int* __restrict__ cnt, int n, int* __restrict__ rowptr,
       int* __restrict__ cursor, float* __restrict__ dinv,
       int* bval, int* bflag)
{
    __shared__ int wsum[8];
    __shared__ int s_base;
    int b = blockIdx.x, tid = threadIdx.x, lane = tid & 31, wid = tid >> 5;
    int i0 = b * SCAN_CH + 2 * tid;
    int c0 = (i0     < n) ? cnt[i0]     : 0;
    int c1 = (i0 + 1 < n) ? cnt[i0 + 1] : 0;
    int s = c0 + c1;
    int x = s;
#pragma unroll
    for (int d = 1; d < 32; d <<= 1) {
        int t = __shfl_up_sync(~0u, x, d);
        if (lane >= d) x += t;
    }
    if (lane == 31) wsum[wid] = x;
    __syncthreads();
    if (wid == 0 && lane < 8) {
        int ws = wsum[lane];
#pragma unroll
        for (int d = 1; d < 8; d <<= 1) {
            int t = __shfl_up_sync(0xFF, ws, d);
            if (lane >= d) ws += t;
        }
        wsum[lane] = ws;
    }
    __syncthreads();
    int ex_local = x - s + (wid ? wsum[wid - 1] : 0);
    int block_total = wsum[7];

    if (tid == 0) {
        atomicExch(&bval[b], block_total);
        __threadfence();
        atomicExch(&bflag[b], 1);
        if (b == 0) rowptr[0] = 0;
    }
    if (wid == 0) {
        int part = 0;
        for (int j = lane; j < b; j += 32) {
            while (atomicAdd(&bflag[j], 0) == 0) {}
            part += atomicAdd(&bval[j], 0);
        }
#pragma unroll
        for (int d = 16; d; d >>= 1) part += __shfl_xor_sync(~0u, part, d);
        if (lane == 0) s_base = part;
    }
    __syncthreads();
    int ex = ex_local + s_base;
    if (i0 < n) {
        cursor[i0]     = ex;
        rowptr[i0 + 1] = ex + c0;
        dinv[i0]       = rsqrtf((float)(c0 + 1));
    }
    if (i0 + 1 < n) {
        cursor[i0 + 1] = ex + c0;
        rowptr[i0 + 2] = ex + c0 + c1;
        dinv[i0 + 1]   = rsqrtf((float)(c1 + 1));
    }
}

__global__ void k_fill(const int* __restrict__ ei, int E,
                       int* __restrict__ cursor, int* __restrict__ col)
{
    int e = blockIdx.x * blockDim.x + threadIdx.x;
    if (e >= E) return;
    int s = ei[e], d = ei[E + e];
    int slot = atomicAdd(&cursor[d], 1);
    col[slot] = s;
}

// ---------------------------------------------------------------------------
// GEMM1 (tensor, 3-pass hi/lo): z = scaler(x) @ W1  (no dinv)
// 3 blocks/SM for DRAM x-stream occupancy.
// ---------------------------------------------------------------------------
__global__ void __launch_bounds__(256, 3)
k_gemm1(const float* __restrict__ A,
        const __half* __restrict__ Wh, const __half* __restrict__ Wl,
        const float* __restrict__ mean, const float* __restrict__ invstd,
        __half* __restrict__ out, int n)
{
    constexpr int AL = 72;
    constexpr int WL = 104;
    __shared__ __align__(16) __half As_hi[128 * AL];
    __shared__ __align__(16) __half As_lo[128 * AL];
    __shared__ __align__(16) __half Ws_hi[64 * WL];
    __shared__ __align__(16) __half Ws_lo[64 * WL];

    const int tid = threadIdx.x, w = tid >> 5;
    const int row0 = blockIdx.x * 128;
    const int arow = tid >> 1, ahalf = tid & 1;
    const int grow = row0 + arow;
    const bool aok = grow < n;
    const bool active = (row0 + w * 16) < n;

    wmma::fragment<wmma::accumulator, 16, 16, 16, float> acc[6];
#pragma unroll
    for (int c = 0; c < 6; c++) wmma::fill_fragment(acc[c], 0.0f);

#pragma unroll 1
    for (int kc = 0; kc < IN_DIM; kc += 64) {
        const float* Ap = A + (size_t)grow * IN_DIM + kc + ahalf * 32;
#pragma unroll
        for (int jj = 0; jj < 4; jj++) {
            __half hi8[8], lo8[8];
#pragma unroll
            for (int j = 0; j < 2; j++) {
                float4 v = aok ? *(const float4*)(Ap + jj * 8 + j * 4)
                               : make_float4(0.f, 0.f, 0.f, 0.f);
                int kg = kc + ahalf * 32 + jj * 8 + j * 4;
                float4 m  = *(const float4*)(mean + kg);
                float4 is = *(const float4*)(invstd + kg);
                float vv[4] = {(v.x - m.x) * is.x, (v.y - m.y) * is.y,
                               (v.z - m.z) * is.z, (v.w - m.w) * is.w};
#pragma unroll
                for (int q = 0; q < 4; q++) {
                    __half h = __float2half_rn(vv[q]);
                    hi8[j * 4 + q] = h;
                    lo8[j * 4 + q] = __float2half_rn(vv[q] - __half2float(h));
                }
            }
            int off = arow * AL + ahalf * 32 + jj * 8;
            *(uint4*)&As_hi[off] = *(const uint4*)hi8;
            *(uint4*)&As_lo[off] = *(const uint4*)lo8;
        }
#pragma unroll
        for (int i = tid; i < 768; i += 256) {
            int r = i / 12, c8 = i % 12;
            size_t gsrc = (size_t)(kc + r) * HID + c8 * 8;
            int sdst = r * WL + c8 * 8;
            *(uint4*)&Ws_hi[sdst] = *(const uint4*)(Wh + gsrc);
            *(uint4*)&Ws_lo[sdst] = *(const uint4*)(Wl + gsrc);
        }
        __syncthreads();

        if (active) {
#pragma unroll
            for (int kk = 0; kk < 4; kk++) {
                wmma::fragment<wmma::matrix_a, 16, 16, 16, __half, wmma::row_major> fa_hi, fa_lo;
                wmma::load_matrix_sync(fa_hi, &As_hi[(w * 16) * AL + kk * 16], AL);
                wmma::load_matrix_sync(fa_lo, &As_lo[(w * 16) * AL + kk * 16], AL);
#pragma unroll
                for (int c = 0; c < 6; c++) {
                    wmma::fragment<wmma::matrix_b, 16, 16, 16, __half, wmma::row_major> fb_hi, fb_lo;
                    wmma::load_matrix_sync(fb_hi, &Ws_hi[(kk * 16) * WL + c * 16], WL);
                    wmma::load_matrix_sync(fb_lo, &Ws_lo[(kk * 16) * WL + c * 16], WL);
                    wmma::mma_sync(acc[c], fa_hi, fb_hi, acc[c]);
                    wmma::mma_sync(acc[c], fa_lo, fb_hi, acc[c]);
                    wmma::mma_sync(acc[c], fa_hi, fb_lo, acc[c]);
                }
            }
        }
        __syncthreads();
    }

    if (active) {
        wmma::fragment<wmma::accumulator, 16, 16, 16, __half> hacc;
#pragma unroll
        for (int c = 0; c < 6; c++) {
#pragma unroll
            for (int i = 0; i < hacc.num_elements; i++)
                hacc.x[i] = __float2half_rn(acc[c].x[i]);
            wmma::store_matrix_sync(out + (size_t)(row0 + w * 16) * HID + c * 16,
                                    hacc, HID, wmma::mem_row_major);
        }
    }
}

// ---------------------------------------------------------------------------
// GEMM2 (tensor, 2-pass): z2 = hh (fp16 exact) @ W2(hi+lo)
// 3 blocks/SM (66.5KB smem x3 = 199.5KB < 228KB) for L2 A-stream occupancy.
// ---------------------------------------------------------------------------
__global__ void __launch_bounds__(256, 3)
k_gemm2(const __half* __restrict__ Ah,
        const __half* __restrict__ Wh, const __half* __restrict__ Wl,
        __half* __restrict__ out, int n)
{
    constexpr int AL = 104;
    constexpr int WL = 104;
    __shared__ __align__(16) __half As[128 * AL];
    __shared__ __align__(16) __half Ws_hi[96 * WL];
    __shared__ __align__(16) __half Ws_lo[96 * WL];

    const int tid = threadIdx.x, w = tid >> 5;
    const int row0 = blockIdx.x * 128;
    const bool active = (row0 + w * 16) < n;

#pragma unroll
    for (int i = tid; i < 1536; i += 256) {
        int r = i / 12, c8 = i % 12;
        int grow = row0 + r;
        uint4 v = (grow < n) ? *(const uint4*)(Ah + (size_t)grow * HID + c8 * 8)
                             : make_uint4(0, 0, 0, 0);
        *(uint4*)&As[r * AL + c8 * 8] = v;
    }
#pragma unroll
    for (int i = tid; i < 1152; i += 256) {
        int r = i / 12, c8 = i % 12;
        size_t gsrc = (size_t)r * HID + c8 * 8;
        int sdst = r * WL + c8 * 8;
        *(uint4*)&Ws_hi[sdst] = *(const uint4*)(Wh + gsrc);
        *(uint4*)&Ws_lo[sdst] = *(const uint4*)(Wl + gsrc);
    }
    __syncthreads();

    if (active) {
        wmma::fragment<wmma::accumulator, 16, 16, 16, float> acc[6];
#pragma unroll
        for (int c = 0; c < 6; c++) wmma::fill_fragment(acc[c], 0.0f);

#pragma unroll
        for (int kk = 0; kk < 6; kk++) {
            wmma::fragment<wmma::matrix_a, 16, 16, 16, __half, wmma::row_major> fa;
            wmma::load_matrix_sync(fa, &As[(w * 16) * AL + kk * 16], AL);
#pragma unroll
            for (int c = 0; c < 6; c++) {
                wmma::fragment<wmma::matrix_b, 16, 16, 16, __half, wmma::row_major> fb_hi, fb_lo;
                wmma::load_matrix_sync(fb_hi, &Ws_hi[(kk * 16) * WL + c * 16], WL);
                wmma::load_matrix_sync(fb_lo, &Ws_lo[(kk * 16) * WL + c * 16], WL);
                wmma::mma_sync(acc[c], fa, fb_hi, acc[c]);
                wmma::mma_sync(acc[c], fa, fb_lo, acc[c]);
            }
        }

        wmma::fragment<wmma::accumulator, 16, 16, 16, __half> hacc;
#pragma unroll
        for (int c = 0; c < 6; c++) {
#pragma unroll
            for (int i = 0; i < hacc.num_elements; i++)
                hacc.x[i] = __float2half_rn(acc[c].x[i]);
            wmma::store_matrix_sync(out + (size_t)(row0 + w * 16) * HID + c * 16,
                                    hacc, HID, wmma::mem_row_major);
        }
    }
}

// ---------------------------------------------------------------------------
// Gather helpers
// ---------------------------------------------------------------------------
__device__ __forceinline__ void fma_u4(float* acc, uint4 u, float ds) {
    __half2* hp = (__half2*)&u;
#pragma unroll
    for (int w = 0; w < 4; w++) {
        float2 f = __half22float2(hp[w]);
        acc[2 * w]     = fmaf(ds, f.x, acc[2 * w]);
        acc[2 * w + 1] = fmaf(ds, f.y, acc[2 * w + 1]);
    }
}
__device__ __forceinline__ void scale_u4(float* acc, uint4 u, float ds) {
    __half2* hp = (__half2*)&u;
#pragma unroll
    for (int w = 0; w < 4; w++) {
        float2 f = __half22float2(hp[w]);
        acc[2 * w]     = ds * f.x;
        acc[2 * w + 1] = ds * f.y;
    }
}
__device__ __forceinline__ void add_u4(float* acc, uint4 u) {
    __half2* hp = (__half2*)&u;
#pragma unroll
    for (int w = 0; w < 4; w++) {
        float2 f = __half22float2(hp[w]);
        acc[2 * w]     += f.x;
        acc[2 * w + 1] += f.y;
    }
}
__device__ __forceinline__ void init_u4(float* acc, uint4 u) {
    __half2* hp = (__half2*)&u;
#pragma unroll
    for (int w = 0; w < 4; w++) {
        float2 f = __half22float2(hp[w]);
        acc[2 * w]     = f.x;
        acc[2 * w + 1] = f.y;
    }
}

// Gather 1 (z has NO dinv): acc = dinv[v]*z[v] + sum dinv[s]*z[s];
// hh = dinv[v]*relu(dinv[v]*acc + b1), fp16.
__global__ void __launch_bounds__(256)
k_gather_br(const int* __restrict__ rowptr, const int* __restrict__ col,
            const float* __restrict__ dinv, const __half* __restrict__ z,
            const float* __restrict__ bias, __half* __restrict__ h, int n)
{
    int t = blockIdx.x * blockDim.x + threadIdx.x;
    int v = t >> 2, part = t & 3;
    if (v >= n) return;
    int beg = rowptr[v], end = rowptr[v + 1];
    float dv = dinv[v];
    float acc[24];
    {
        const uint4* self = (const uint4*)(z + (size_t)v * HID + part * 24);
        uint4 u0 = self[0], u1 = self[1], u2 = self[2];
        scale_u4(acc, u0, dv); scale_u4(acc + 8, u1, dv); scale_u4(acc + 16, u2, dv);
    }
    int j = beg;
    for (; j + 1 < end; j += 2) {
        int s0 = col[j], s1 = col[j + 1];
        float d0 = dinv[s0], d1 = dinv[s1];
        const uint4* p0 = (const uint4*)(z + (size_t)s0 * HID + part * 24);
        const uint4* p1 = (const uint4*)(z + (size_t)s1 * HID + part * 24);
        uint4 a0 = p0[0], a1 = p0[1], a2 = p0[2];
        uint4 b0 = p1[0], b1 = p1[1], b2 = p1[2];
        fma_u4(acc, a0, d0); fma_u4(acc + 8, a1, d0); fma_u4(acc + 16, a2, d0);
        fma_u4(acc, b0, d1); fma_u4(acc + 8, b1, d1); fma_u4(acc + 16, b2, d1);
    }
    if (j < end) {
        int s0 = col[j];
        float d0 = dinv[s0];
        const uint4* p0 = (const uint4*)(z + (size_t)s0 * HID + part * 24);
        uint4 a0 = p0[0], a1 = p0[1], a2 = p0[2];
        fma_u4(acc, a0, d0); fma_u4(acc + 8, a1, d0); fma_u4(acc + 16, a2, d0);
    }
    int kb = part * 24;
    __half o[24];
#pragma unroll
    for (int i = 0; i < 24; i++)
        o[i] = __float2half_rn(dv * fmaxf(fmaf(dv, acc[i], bias[kb + i]), 0.f));
    uint4* hp = (uint4*)(h + (size_t)v * HID + kb);
    hp[0] = *(const uint4*)&o[0];
    hp[1] = *(const uint4*)&o[8];
    hp[2] = *(const uint4*)&o[16];
}

// Gather 2 (z2 has per-row dinv folded): plain sum,
// s[v] = dinv[v] * dot(relu(dinv[v]*acc + b2), w3v)
__global__ void __launch_bounds__(256)
k_gather_gemv(const int* __restrict__ rowptr, const int* __restrict__ col,
              const float* __restrict__ dinv, const __half* __restrict__ z,
              const float* __restrict__ bias, const float* __restrict__ w3v,
              float* __restrict__ s, int n)
{
    int t = blockIdx.x * blockDim.x + threadIdx.x;
    int v = t >> 2, part = t & 3;
    if (v >= n) return;
    int beg = rowptr[v], end = rowptr[v + 1];
    float acc[24];
    {
        const uint4* self = (const uint4*)(z + (size_t)v * HID + part * 24);
        uint4 u0 = self[0], u1 = self[1], u2 = self[2];
        init_u4(acc, u0); init_u4(acc + 8, u1); init_u4(acc + 16, u2);
    }
    int j = beg;
    for (; j + 1 < end; j += 2) {
        int s0 = col[j], s1 = col[j + 1];
        const uint4* p0 = (const uint4*)(z + (size_t)s0 * HID + part * 24);
        const uint4* p1 = (const uint4*)(z + (size_t)s1 * HID + part * 24);
        uint4 a0 = p0[0], a1 = p0[1], a2 = p0[2];
        uint4 b0 = p1[0], b1 = p1[1], b2 = p1[2];
        add_u4(acc, a0); add_u4(acc + 8, a1); add_u4(acc + 16, a2);
        add_u4(acc, b0); add_u4(acc + 8, b1); add_u4(acc + 16, b2);
    }
    if (j < end) {
        const uint4* p0 = (const uint4*)(z + (size_t)col[j] * HID + part * 24);
        uint4 a0 = p0[0], a1 = p0[1], a2 = p0[2];
        add_u4(acc, a0); add_u4(acc + 8, a1); add_u4(acc + 16, a2);
    }
    float dv = dinv[v];
    int kb = part * 24;
    float partial = 0.f;
#pragma unroll
    for (int i = 0; i < 24; i++) {
        float hv = fmaxf(fmaf(dv, acc[i], bias[kb + i]), 0.f);
        partial = fmaf(hv, w3v[kb + i], partial);
    }
    partial += __shfl_xor_sync(0xffffffffu, partial, 1);
    partial += __shfl_xor_sync(0xffffffffu, partial, 2);
    if (part == 0) s[v] = dv * partial;
}

// Final scalar prop
__global__ void __launch_bounds__(256)
k_out(const int* __restrict__ rowptr, const int* __restrict__ col,
      const float* __restrict__ dinv, const float* __restrict__ s,
      const float* __restrict__ w3v, float* __restrict__ out, int n)
{
    int t = blockIdx.x * blockDim.x + threadIdx.x;
    int v = t >> 3, part = t & 7;
    if (v >= n) return;
    int beg = rowptr[v], end = rowptr[v + 1];
    float acc = 0.f;
    for (int j = beg + part; j < end; j += 8)
        acc += s[col[j]];
    acc += __shfl_xor_sync(0xffffffffu, acc, 4);
    acc += __shfl_xor_sync(0xffffffffu, acc, 2);
    acc += __shfl_xor_sync(0xffffffffu, acc, 1);
    if (part == 0) out[v] = fmaf(dinv[v], acc + s[v], w3v[HID]);
}

// ---------------------------------------------------------------------------
// Host launch: fork GEMM1 vs CSR build; split tail.
// ---------------------------------------------------------------------------
extern "C" void kernel_launch(void* const* d_in, const int* in_sizes, int n_in,
                              void* d_out, int out_size)
{
    const float* x    = (const float*)d_in[0];
    const int*   ei   = (const int*)d_in[1];
    // d_in[2] = PQVA_mask (deterministic: output = column 1)
    const float* mean = (const float*)d_in[3];
    const float* stdv = (const float*)d_in[4];
    const float* W1   = (const float*)d_in[5];
    const float* b1   = (const float*)d_in[6];
    const float* W2   = (const float*)d_in[7];
    const float* b2   = (const float*)d_in[8];
    const float* W3   = (const float*)d_in[9];
    const float* b3   = (const float*)d_in[10];
    const float* Wout = (const float*)d_in[11];
    const float* bout = (const float*)d_in[12];
    float* out = (float*)d_out;

    const int N = in_sizes[0] / IN_DIM;
    const int E = in_sizes[1] / 2;

    __half *zh, *hh, *w1h, *w1l, *w2h, *w2l;
    float *sv, *dinv, *invstd, *w3v;
    int *cnt, *rowptr, *cursor, *colb, *bval, *bflag;
    cudaGetSymbolAddress((void**)&zh, g_zh);
    cudaGetSymbolAddress((void**)&hh, g_hh);
    cudaGetSymbolAddress((void**)&w1h, g_w1h);
    cudaGetSymbolAddress((void**)&w1l, g_w1l);
    cudaGetSymbolAddress((void**)&w2h, g_w2h);
    cudaGetSymbolAddress((void**)&w2l, g_w2l);
    cudaGetSymbolAddress((void**)&sv, g_s);
    cudaGetSymbolAddress((void**)&dinv, g_dinv);
    cudaGetSymbolAddress((void**)&invstd, g_invstd);
    cudaGetSymbolAddress((void**)&w3v, g_w3v);
    cudaGetSymbolAddress((void**)&cnt, g_cnt);
    cudaGetSymbolAddress((void**)&rowptr, g_rowptr);
    cudaGetSymbolAddress((void**)&cursor, g_cursor);
    cudaGetSymbolAddress((void**)&colb, g_col);
    cudaGetSymbolAddress((void**)&bval, g_bval);
    cudaGetSymbolAddress((void**)&bflag, g_bflag);

    const int TB = 256;
    int nb_n = (N + TB - 1) / TB;
    int nb_e = (E + TB - 1) / TB;
    int nb_gemm = (N + 127) / 128;
    int nb_g4 = (N * 4 + TB - 1) / TB;
    int nb_g8 = (N * 8 + TB - 1) / TB;
    int nb_scan = (N + SCAN_CH - 1) / SCAN_CH;

    cudaStream_t s2;
    cudaStreamCreateWithFlags(&s2, cudaStreamNonBlocking);
    cudaEvent_t eFork, eJoin;
    cudaEventCreateWithFlags(&eFork, cudaEventDisableTiming);
    cudaEventCreateWithFlags(&eJoin, cudaEventDisableTiming);

    k_pre<<<nb_n, TB>>>(cnt, N, bflag, stdv, invstd, W1, W2, W3, b3,
                        Wout, bout, w3v, w1h, w1l, w2h, w2l);
    cudaEventRecord(eFork, 0);
    cudaStreamWaitEvent(s2, eFork, 0);

    // Branch A (side stream): GEMM1
    k_gemm1<<<nb_gemm, TB, 0, s2>>>(x, w1h, w1l, mean, invstd, zh, N);
    cudaEventRecord(eJoin, s2);

    // Branch B (main stream): CSR build
    k_count<<<nb_e, TB>>>(ei, E, cnt);
    k_scan<<<nb_scan, TB>>>(cnt, N, rowptr, cursor, dinv, bval, bflag);
    k_fill<<<nb_e, TB>>>(ei, E, cursor, colb);

    cudaStreamWaitEvent(0, eJoin, 0);

    // Tail
    k_gather_br<<<nb_g4, TB>>>(rowptr, colb, dinv, zh, b1, hh, N);
    k_gemm2<<<nb_gemm, TB>>>(hh, w2h, w2l, zh, N);
    k_gather_gemv<<<nb_g4, TB>>>(rowptr, colb, dinv, zh, b2, w3v, sv, N);
    k_out<<<nb_g8, TB>>>(rowptr, colb, dinv, sv, w3v, out, N);
}